// round 9
// baseline (speedup 1.0000x reference)
#include <cuda_runtime.h>
#include <cstdint>
#include <math.h>

#define BDIM 2
#define TSEQ 2048
#define DMODEL 1024
#define NHEADS 16
#define DK 64
#define MTOK (BDIM * TSEQ)   // 4096

// -------- scratch (device globals; no allocation allowed) --------
__device__ float g_Q[MTOK * DMODEL];
__device__ float g_K[MTOK * DMODEL];
__device__ float g_V[MTOK * DMODEL];
__device__ float g_ctx[MTOK * DMODEL];

// ============================================================================
// helpers
// ============================================================================
__device__ __forceinline__ uint32_t smem_u32(const void* p) {
    uint32_t a;
    asm("{ .reg .u64 t; cvta.to.shared.u64 t, %1; cvt.u32.u64 %0, t; }" : "=r"(a) : "l"(p));
    return a;
}

__device__ __forceinline__ uint32_t f2tf32(float f) {
    uint32_t r;
    asm("cvt.rna.tf32.f32 %0, %1;" : "=r"(r) : "f"(f));
    return r;
}

__device__ __forceinline__ void mma_tf32(float* d, const uint32_t* a,
                                         uint32_t b0, uint32_t b1) {
    asm volatile(
        "mma.sync.aligned.m16n8k8.row.col.f32.tf32.tf32.f32 "
        "{%0,%1,%2,%3}, {%4,%5,%6,%7}, {%8,%9}, {%0,%1,%2,%3};"
        : "+f"(d[0]), "+f"(d[1]), "+f"(d[2]), "+f"(d[3])
        : "r"(a[0]), "r"(a[1]), "r"(a[2]), "r"(a[3]), "r"(b0), "r"(b1));
}

#define CP_ASYNC16(dst, src) \
    asm volatile("cp.async.cg.shared.global [%0], [%1], 16;" \
                 :: "r"((uint32_t)(dst)), "l"(src) : "memory")
#define CP_COMMIT() asm volatile("cp.async.commit_group;" ::: "memory")
#define CP_WAIT2()  asm volatile("cp.async.wait_group 2;" ::: "memory")
#define CP_WAIT1()  asm volatile("cp.async.wait_group 1;" ::: "memory")
#define CP_WAIT0()  asm volatile("cp.async.wait_group 0;" ::: "memory")

// ============================================================================
// tf32 mma.sync GEMM v2: Y[m,n] = sum_k A[m,k]*W[n,k] + bias[n]
// CTA 128x128, 128 threads (4 warps 2x2), warp tile 64x64 (M=4, N=8 frags),
// BK=32, 3-stage cp.async pipeline, smem [128][36] per array per stage.
// blockIdx.z selects (W, bias, Y).
// ============================================================================
#define GBK 32
#define NCHUNK (DMODEL / GBK)      // 32
#define SROW 36
#define STAGE_F (128 * SROW)       // floats per array per stage (4608)
#define GEMM_SMEM (3 * 2 * STAGE_F * 4)   // 110592 bytes

__global__ __launch_bounds__(128, 2)
void gemm_tc_kernel(const float* __restrict__ A,
                    const float* __restrict__ W0, const float* __restrict__ W1,
                    const float* __restrict__ W2,
                    const float* __restrict__ b0, const float* __restrict__ b1,
                    const float* __restrict__ b2,
                    float* __restrict__ Y0, float* __restrict__ Y1,
                    float* __restrict__ Y2)
{
    extern __shared__ float smem[];   // stage s: A at s*2*STAGE_F, W at +STAGE_F

    const float* W = W0; const float* bias = b0; float* Y = Y0;
    if (blockIdx.z == 1) { W = W1; bias = b1; Y = Y1; }
    else if (blockIdx.z == 2) { W = W2; bias = b2; Y = Y2; }

    const int tid  = threadIdx.x;
    const int wid  = tid >> 5;
    const int lane = tid & 31;
    const int m0 = blockIdx.y * 128;
    const int n0 = blockIdx.x * 128;

    const int m_warp = (wid & 1) * 64;
    const int n_warp = (wid >> 1) * 64;
    const int c4 = lane & 3;
    const int g8 = lane >> 2;

    // loader: 1 row of A + 1 row of W per thread per chunk (8 cp.async16 each)
    const int rowL = tid;
    const float* Abase = A + (size_t)(m0 + rowL) * DMODEL;
    const float* Wbase = W + (size_t)(n0 + rowL) * DMODEL;
    uint32_t sArow[3], sWrow[3];
#pragma unroll
    for (int s = 0; s < 3; ++s) {
        sArow[s] = smem_u32(smem + s * 2 * STAGE_F) + (uint32_t)(rowL * SROW) * 4u;
        sWrow[s] = sArow[s] + STAGE_F * 4u;
    }

#define LOAD_CHUNK(c, s) do {                                                 \
    const float* _ga = Abase + (c) * GBK;                                     \
    const float* _gw = Wbase + (c) * GBK;                                     \
    uint32_t _da = sArow[s], _dw = sWrow[s];                                  \
    CP_ASYNC16(_da,       _ga);      CP_ASYNC16(_da + 16,  _ga + 4);          \
    CP_ASYNC16(_da + 32,  _ga + 8);  CP_ASYNC16(_da + 48,  _ga + 12);         \
    CP_ASYNC16(_da + 64,  _ga + 16); CP_ASYNC16(_da + 80,  _ga + 20);         \
    CP_ASYNC16(_da + 96,  _ga + 24); CP_ASYNC16(_da + 112, _ga + 28);         \
    CP_ASYNC16(_dw,       _gw);      CP_ASYNC16(_dw + 16,  _gw + 4);          \
    CP_ASYNC16(_dw + 32,  _gw + 8);  CP_ASYNC16(_dw + 48,  _gw + 12);         \
    CP_ASYNC16(_dw + 64,  _gw + 16); CP_ASYNC16(_dw + 80,  _gw + 20);         \
    CP_ASYNC16(_dw + 96,  _gw + 24); CP_ASYNC16(_dw + 112, _gw + 28);         \
    CP_COMMIT();                                                              \
} while (0)

    float acc[4][8][4];
#pragma unroll
    for (int i = 0; i < 4; ++i)
#pragma unroll
        for (int j = 0; j < 8; ++j)
#pragma unroll
            for (int r = 0; r < 4; ++r) acc[i][j][r] = 0.f;

    LOAD_CHUNK(0, 0);
    LOAD_CHUNK(1, 1);
    LOAD_CHUNK(2, 2);

    int s = 0;
#pragma unroll 1
    for (int c = 0; c < NCHUNK; ++c) {
        if (c <= NCHUNK - 3)      CP_WAIT2();
        else if (c == NCHUNK - 2) CP_WAIT1();
        else                      CP_WAIT0();
        __syncthreads();

        const float* Ac = smem + s * 2 * STAGE_F;
        const float* Wc = Ac + STAGE_F;

#pragma unroll
        for (int ks = 0; ks < 4; ++ks) {
            const int kk = ks * 8 + c4;
            uint32_t a[4][4];
#pragma unroll
            for (int mt = 0; mt < 4; ++mt) {
                const int rm = m_warp + mt * 16 + g8;
                a[mt][0] = f2tf32(Ac[rm * SROW + kk]);
                a[mt][1] = f2tf32(Ac[(rm + 8) * SROW + kk]);
                a[mt][2] = f2tf32(Ac[rm * SROW + kk + 4]);
                a[mt][3] = f2tf32(Ac[(rm + 8) * SROW + kk + 4]);
            }
#pragma unroll
            for (int nt = 0; nt < 8; ++nt) {
                const int rn = n_warp + nt * 8 + g8;
                uint32_t bb0 = f2tf32(Wc[rn * SROW + kk]);
                uint32_t bb1 = f2tf32(Wc[rn * SROW + kk + 4]);
                mma_tf32(acc[0][nt], a[0], bb0, bb1);
                mma_tf32(acc[1][nt], a[1], bb0, bb1);
                mma_tf32(acc[2][nt], a[2], bb0, bb1);
                mma_tf32(acc[3][nt], a[3], bb0, bb1);
            }
        }

        __syncthreads();
        if (c + 3 < NCHUNK) LOAD_CHUNK(c + 3, s);
        s = (s == 2) ? 0 : s + 1;
    }
#undef LOAD_CHUNK

    // epilogue
#pragma unroll
    for (int mt = 0; mt < 4; ++mt) {
        const int row = m0 + m_warp + mt * 16 + g8;
#pragma unroll
        for (int nt = 0; nt < 8; ++nt) {
            const int col = n0 + n_warp + nt * 8 + c4 * 2;
            const float bx = bias[col], by = bias[col + 1];
            float2 r0 = make_float2(acc[mt][nt][0] + bx, acc[mt][nt][1] + by);
            float2 r1 = make_float2(acc[mt][nt][2] + bx, acc[mt][nt][3] + by);
            *(float2*)(Y + (size_t)row * DMODEL + col)       = r0;
            *(float2*)(Y + (size_t)(row + 8) * DMODEL + col) = r1;
        }
    }
}

// ============================================================================
// Tensor-core causal flash attention (tf32 mma.sync) — unchanged from R8.
// ============================================================================
#define ABK 32
#define KSTR 68
#define VSTR 36
#define PSTR 36
#define ATTN_SMEM (13568 * 4)

__global__ __launch_bounds__(256)
void attn_tc_kernel(const float* __restrict__ Q, const float* __restrict__ K,
                    const float* __restrict__ V, float* __restrict__ ctx)
{
    extern __shared__ float sm[];
    float* KsB[2] = { sm, sm + 32 * KSTR };
    uint32_t* VtB[2] = { (uint32_t*)(sm + 2 * 32 * KSTR),
                         (uint32_t*)(sm + 2 * 32 * KSTR + 64 * VSTR) };
    uint32_t* Pw = (uint32_t*)(sm + 2 * 32 * KSTR + 2 * 64 * VSTR);

    const int tid  = threadIdx.x;
    const int wid  = tid >> 5;
    const int lane = tid & 31;
    const int g8 = lane >> 2;
    const int c4 = lane & 3;

    const int bq = blockIdx.x;
    const int h  = blockIdx.y;
    const int b  = blockIdx.z;
    const int wq0 = bq * 128 + wid * 16;
    const size_t seqbase = ((size_t)b * TSEQ) * DMODEL + (size_t)h * DK;

    uint32_t* Pme = Pw + wid * 16 * PSTR;

    uint32_t qa[8][4];
    {
        const float* qlo = Q + seqbase + (size_t)(wq0 + g8) * DMODEL;
        const float* qhi = qlo + 8 * DMODEL;
#pragma unroll
        for (int ks = 0; ks < 8; ++ks) {
            qa[ks][0] = f2tf32(qlo[8 * ks + c4]     * 0.125f);
            qa[ks][1] = f2tf32(qhi[8 * ks + c4]     * 0.125f);
            qa[ks][2] = f2tf32(qlo[8 * ks + c4 + 4] * 0.125f);
            qa[ks][3] = f2tf32(qhi[8 * ks + c4 + 4] * 0.125f);
        }
    }

    const int ntiles = 4 * bq + 4;

    const int kkey = tid >> 3, kseg = (tid & 7) * 8;
    const int vkey = tid & 31, vseg = (tid >> 5) * 8;
    const uint32_t ks0a = smem_u32(KsB[0]) + (uint32_t)(kkey * KSTR + kseg) * 4u;
    const uint32_t ks1a = smem_u32(KsB[1]) + (uint32_t)(kkey * KSTR + kseg) * 4u;

    {
        const float* kr = K + seqbase + (size_t)kkey * DMODEL + kseg;
        CP_ASYNC16(ks0a, kr); CP_ASYNC16(ks0a + 16, kr + 4);
        CP_COMMIT();
    }
    {
        const float* vr = V + seqbase + (size_t)vkey * DMODEL + vseg;
        float4 a = *(const float4*)vr, c = *(const float4*)(vr + 4);
        uint32_t* Vn = VtB[0];
        Vn[(vseg + 0) * VSTR + vkey] = f2tf32(a.x);
        Vn[(vseg + 1) * VSTR + vkey] = f2tf32(a.y);
        Vn[(vseg + 2) * VSTR + vkey] = f2tf32(a.z);
        Vn[(vseg + 3) * VSTR + vkey] = f2tf32(a.w);
        Vn[(vseg + 4) * VSTR + vkey] = f2tf32(c.x);
        Vn[(vseg + 5) * VSTR + vkey] = f2tf32(c.y);
        Vn[(vseg + 6) * VSTR + vkey] = f2tf32(c.z);
        Vn[(vseg + 7) * VSTR + vkey] = f2tf32(c.w);
    }
    float4 va, vb;
    {
        const float* kr = K + seqbase + (size_t)(ABK + kkey) * DMODEL + kseg;
        CP_ASYNC16(ks1a, kr); CP_ASYNC16(ks1a + 16, kr + 4);
        CP_COMMIT();
        const float* vr = V + seqbase + (size_t)(ABK + vkey) * DMODEL + vseg;
        va = *(const float4*)vr; vb = *(const float4*)(vr + 4);
    }
    CP_WAIT1();
    __syncthreads();

    float m0 = -1e30f, m1 = -1e30f, l0 = 0.f, l1 = 0.f;
    float o[8][4];
#pragma unroll
    for (int nf = 0; nf < 8; ++nf)
#pragma unroll
        for (int r = 0; r < 4; ++r) o[nf][r] = 0.f;

    const int rlo = wq0 + g8, rhi = rlo + 8;

#pragma unroll 1
    for (int it = 0; it < ntiles; ++it) {
        const int k0 = it * ABK;
        const float*    Kc = KsB[it & 1];
        const uint32_t* Vc = VtB[it & 1];

        float4 na, nb;
        const bool have2 = (it + 2 < ntiles);
        if (have2) {
            const float* vr = V + seqbase + (size_t)((it + 2) * ABK + vkey) * DMODEL + vseg;
            na = *(const float4*)vr; nb = *(const float4*)(vr + 4);
        }

        if (k0 <= wq0 + 15) {
            float s[4][4];
#pragma unroll
            for (int nf = 0; nf < 4; ++nf)
#pragma unroll
                for (int r = 0; r < 4; ++r) s[nf][r] = 0.f;
#pragma unroll
            for (int ks = 0; ks < 8; ++ks) {
#pragma unroll
                for (int nf = 0; nf < 4; ++nf) {
                    const float* kp = Kc + (nf * 8 + g8) * KSTR + ks * 8 + c4;
                    uint32_t bb0 = f2tf32(kp[0]);
                    uint32_t bb1 = f2tf32(kp[4]);
                    mma_tf32(s[nf], qa[ks], bb0, bb1);
                }
            }

            if (k0 + ABK - 1 > wq0) {
#pragma unroll
                for (int nf = 0; nf < 4; ++nf) {
                    const int kg = k0 + nf * 8 + 2 * c4;
                    if (kg     > rlo) s[nf][0] = -1e30f;
                    if (kg + 1 > rlo) s[nf][1] = -1e30f;
                    if (kg     > rhi) s[nf][2] = -1e30f;
                    if (kg + 1 > rhi) s[nf][3] = -1e30f;
                }
            }

            float tl = -1e30f, th = -1e30f;
#pragma unroll
            for (int nf = 0; nf < 4; ++nf) {
                tl = fmaxf(tl, fmaxf(s[nf][0], s[nf][1]));
                th = fmaxf(th, fmaxf(s[nf][2], s[nf][3]));
            }
            tl = fmaxf(tl, __shfl_xor_sync(0xffffffffu, tl, 1));
            tl = fmaxf(tl, __shfl_xor_sync(0xffffffffu, tl, 2));
            th = fmaxf(th, __shfl_xor_sync(0xffffffffu, th, 1));
            th = fmaxf(th, __shfl_xor_sync(0xffffffffu, th, 2));

            const float mn0 = fmaxf(m0, tl), mn1 = fmaxf(m1, th);
            const float cr0 = __expf(m0 - mn0), cr1 = __expf(m1 - mn1);
            float sl = 0.f, sh = 0.f;
#pragma unroll
            for (int nf = 0; nf < 4; ++nf) {
                float p0 = __expf(s[nf][0] - mn0);
                float p1 = __expf(s[nf][1] - mn0);
                float p2 = __expf(s[nf][2] - mn1);
                float p3 = __expf(s[nf][3] - mn1);
                sl += p0 + p1; sh += p2 + p3;
                Pme[g8 * PSTR + nf * 8 + 2 * c4]           = f2tf32(p0);
                Pme[g8 * PSTR + nf * 8 + 2 * c4 + 1]       = f2tf32(p1);
                Pme[(g8 + 8) * PSTR + nf * 8 + 2 * c4]     = f2tf32(p2);
                Pme[(g8 + 8) * PSTR + nf * 8 + 2 * c4 + 1] = f2tf32(p3);
            }
            sl += __shfl_xor_sync(0xffffffffu, sl, 1);
            sl += __shfl_xor_sync(0xffffffffu, sl, 2);
            sh += __shfl_xor_sync(0xffffffffu, sh, 1);
            sh += __shfl_xor_sync(0xffffffffu, sh, 2);
            l0 = l0 * cr0 + sl;  l1 = l1 * cr1 + sh;
            m0 = mn0;  m1 = mn1;
#pragma unroll
            for (int nf = 0; nf < 8; ++nf) {
                o[nf][0] *= cr0; o[nf][1] *= cr0;
                o[nf][2] *= cr1; o[nf][3] *= cr1;
            }
            __syncwarp();

#pragma unroll
            for (int ks = 0; ks < 4; ++ks) {
                uint32_t a[4];
                a[0] = Pme[g8 * PSTR + ks * 8 + c4];
                a[1] = Pme[(g8 + 8) * PSTR + ks * 8 + c4];
                a[2] = Pme[g8 * PSTR + ks * 8 + c4 + 4];
                a[3] = Pme[(g8 + 8) * PSTR + ks * 8 + c4 + 4];
#pragma unroll
                for (int nf = 0; nf < 8; ++nf) {
                    uint32_t bb0 = Vc[(nf * 8 + g8) * VSTR + ks * 8 + c4];
                    uint32_t bb1 = Vc[(nf * 8 + g8) * VSTR + ks * 8 + c4 + 4];
                    mma_tf32(o[nf], a, bb0, bb1);
                }
            }
        }

        if (it + 1 < ntiles) {
            CP_WAIT0();
            __syncthreads();
            uint32_t* Vn = VtB[(it + 1) & 1];
            Vn[(vseg + 0) * VSTR + vkey] = f2tf32(va.x);
            Vn[(vseg + 1) * VSTR + vkey] = f2tf32(va.y);
            Vn[(vseg + 2) * VSTR + vkey] = f2tf32(va.z);
            Vn[(vseg + 3) * VSTR + vkey] = f2tf32(va.w);
            Vn[(vseg + 4) * VSTR + vkey] = f2tf32(vb.x);
            Vn[(vseg + 5) * VSTR + vkey] = f2tf32(vb.y);
            Vn[(vseg + 6) * VSTR + vkey] = f2tf32(vb.z);
            Vn[(vseg + 7) * VSTR + vkey] = f2tf32(vb.w);
            if (have2) {
                const float* kr = K + seqbase + (size_t)((it + 2) * ABK + kkey) * DMODEL + kseg;
                const uint32_t dst = (it & 1) ? ks1a : ks0a;
                CP_ASYNC16(dst, kr); CP_ASYNC16(dst + 16, kr + 4);
                CP_COMMIT();
                va = na; vb = nb;
            }
            __syncthreads();
        }
    }

    const float inv0 = 1.f / l0, inv1 = 1.f / l1;
    float* olo = ctx + seqbase + (size_t)rlo * DMODEL;
    float* ohi = ctx + seqbase + (size_t)rhi * DMODEL;
#pragma unroll
    for (int nf = 0; nf < 8; ++nf) {
        const int col = nf * 8 + 2 * c4;
        *(float2*)(olo + col) = make_float2(o[nf][0] * inv0, o[nf][1] * inv0);
        *(float2*)(ohi + col) = make_float2(o[nf][2] * inv1, o[nf][3] * inv1);
    }
}

// ============================================================================
// launch
// ============================================================================
extern "C" void kernel_launch(void* const* d_in, const int* in_sizes, int n_in,
                              void* d_out, int out_size)
{
    const float* x  = (const float*)d_in[0];
    const float* Wq = (const float*)d_in[1];
    const float* bq = (const float*)d_in[2];
    const float* Wk = (const float*)d_in[3];
    const float* bk = (const float*)d_in[4];
    const float* Wv = (const float*)d_in[5];
    const float* bv = (const float*)d_in[6];
    const float* Wo = (const float*)d_in[7];
    const float* bo = (const float*)d_in[8];
    float* out = (float*)d_out;

    float *qp, *kp, *vp, *cp;
    cudaGetSymbolAddress((void**)&qp, g_Q);
    cudaGetSymbolAddress((void**)&kp, g_K);
    cudaGetSymbolAddress((void**)&vp, g_V);
    cudaGetSymbolAddress((void**)&cp, g_ctx);

    cudaFuncSetAttribute(gemm_tc_kernel,
                         cudaFuncAttributeMaxDynamicSharedMemorySize, GEMM_SMEM);
    cudaFuncSetAttribute(attn_tc_kernel,
                         cudaFuncAttributeMaxDynamicSharedMemorySize, ATTN_SMEM);

    dim3 qkv_grid(DMODEL / 128, MTOK / 128, 3);   // (8, 32, 3)
    gemm_tc_kernel<<<qkv_grid, 128, GEMM_SMEM>>>(
        x, Wq, Wk, Wv, bq, bk, bv, qp, kp, vp);

    dim3 agrid(TSEQ / 128, NHEADS, BDIM);         // (16, 16, 2)
    attn_tc_kernel<<<agrid, 256, ATTN_SMEM>>>(qp, kp, vp, cp);

    dim3 o_grid(DMODEL / 128, MTOK / 128, 1);
    gemm_tc_kernel<<<o_grid, 128, GEMM_SMEM>>>(
        cp, Wo, Wo, Wo, bo, bo, bo, out, out, out);
}

// round 11
// speedup vs baseline: 1.1049x; 1.1049x over previous
#include <cuda_runtime.h>
#include <cstdint>
#include <math.h>

#define BDIM 2
#define TSEQ 2048
#define DMODEL 1024
#define NHEADS 16
#define DK 64
#define MTOK (BDIM * TSEQ)   // 4096

// -------- scratch (device globals; no allocation allowed) --------
// All intermediate tensors live as tf32 BIT PATTERNS (uint32).
__device__ uint32_t g_xb[MTOK * DMODEL];          // x converted to tf32 bits
__device__ uint32_t g_Wb[4 * DMODEL * DMODEL];    // Wq,Wk,Wv,Wo tf32 bits
__device__ uint32_t g_Q[MTOK * DMODEL];           // Q*0.125 (tf32 bits)
__device__ uint32_t g_K[MTOK * DMODEL];
__device__ uint32_t g_V[MTOK * DMODEL];
__device__ uint32_t g_ctx[MTOK * DMODEL];         // attention out (tf32 bits)

// ============================================================================
// helpers
// ============================================================================
__device__ __forceinline__ uint32_t smem_u32(const void* p) {
    uint32_t a;
    asm("{ .reg .u64 t; cvta.to.shared.u64 t, %1; cvt.u32.u64 %0, t; }" : "=r"(a) : "l"(p));
    return a;
}

__device__ __forceinline__ uint32_t f2tf32(float f) {
    uint32_t r;
    asm("cvt.rna.tf32.f32 %0, %1;" : "=r"(r) : "f"(f));
    return r;
}

__device__ __forceinline__ void mma_tf32(float* d, const uint32_t* a,
                                         uint32_t b0, uint32_t b1) {
    asm volatile(
        "mma.sync.aligned.m16n8k8.row.col.f32.tf32.tf32.f32 "
        "{%0,%1,%2,%3}, {%4,%5,%6,%7}, {%8,%9}, {%0,%1,%2,%3};"
        : "+f"(d[0]), "+f"(d[1]), "+f"(d[2]), "+f"(d[3])
        : "r"(a[0]), "r"(a[1]), "r"(a[2]), "r"(a[3]), "r"(b0), "r"(b1));
}

#define CP_ASYNC16(dst, src) \
    asm volatile("cp.async.cg.shared.global [%0], [%1], 16;" \
                 :: "r"((uint32_t)(dst)), "l"(src) : "memory")
#define CP_COMMIT() asm volatile("cp.async.commit_group;" ::: "memory")
#define CP_WAIT1()  asm volatile("cp.async.wait_group 1;" ::: "memory")
#define CP_WAIT0()  asm volatile("cp.async.wait_group 0;" ::: "memory")

// ============================================================================
// Pre-convert: x (4M) + Wq,Wk,Wv,Wo (4 x 1M) fp32 -> tf32 bits.
// 2M float4 total; one grid-stride-free exact launch (8192 x 256).
// ============================================================================
#define XN4   (MTOK * DMODEL / 4)        // 1048576 = 2^20
#define WN4   (DMODEL * DMODEL / 4)      // 262144  = 2^18

__global__ __launch_bounds__(256)
void cvt_tf32_kernel(const float4* __restrict__ x,
                     const float4* __restrict__ wq, const float4* __restrict__ wk,
                     const float4* __restrict__ wv, const float4* __restrict__ wo,
                     uint4* __restrict__ xb, uint4* __restrict__ wb)
{
    const int i = blockIdx.x * 256 + threadIdx.x;
    const float4* src;
    uint4* dst;
    if (i < XN4) {
        src = x + i; dst = xb + i;
    } else {
        const int j = i - XN4;
        const int w = j >> 18;             // which weight
        const int off = j & (WN4 - 1);
        const float4* ws[4] = { wq, wk, wv, wo };
        src = ws[w] + off;
        dst = wb + (size_t)w * WN4 + off;
    }
    float4 v = *src;
    uint4 u;
    u.x = f2tf32(v.x); u.y = f2tf32(v.y);
    u.z = f2tf32(v.z); u.w = f2tf32(v.w);
    *dst = u;
}

// ============================================================================
// tf32 mma.sync GEMM (R8 shape): Y = A * W^T + bias, operands are tf32 bits.
// CTA 128x128, BK=32, 256 thr (8 warps 4x2), warp tile 32x64, double buffer.
// STORE_BITS=1: Y is uint32 tf32 bits of (acc+bias)*scale; else fp32.
// ============================================================================
#define GBK 32
#define NCHUNK (DMODEL / GBK)      // 32
#define SROW 36
#define TILE_F (128 * SROW)
#define GEMM_SMEM (4 * TILE_F * 4) // 73728 bytes

template<int STORE_BITS>
__global__ __launch_bounds__(256)
void gemm_tc_kernel(const uint32_t* __restrict__ A,
                    const uint32_t* __restrict__ W0, const uint32_t* __restrict__ W1,
                    const uint32_t* __restrict__ W2,
                    const float* __restrict__ b0, const float* __restrict__ b1,
                    const float* __restrict__ b2,
                    void* __restrict__ Y0, void* __restrict__ Y1,
                    void* __restrict__ Y2,
                    float s0, float s1, float s2)
{
    extern __shared__ uint32_t smem[];
    uint32_t* As0 = smem;
    uint32_t* Ws0 = As0 + TILE_F;
    uint32_t* As1 = Ws0 + TILE_F;
    uint32_t* Ws1 = As1 + TILE_F;

    const uint32_t* W = W0; const float* bias = b0; void* Y = Y0; float scale = s0;
    if (blockIdx.z == 1) { W = W1; bias = b1; Y = Y1; scale = s1; }
    else if (blockIdx.z == 2) { W = W2; bias = b2; Y = Y2; scale = s2; }

    const int tid  = threadIdx.x;
    const int wid  = tid >> 5;
    const int lane = tid & 31;
    const int m0 = blockIdx.y * 128;
    const int n0 = blockIdx.x * 128;

    const int m_warp = (wid & 3) * 32;
    const int n_warp = (wid >> 2) * 64;
    const int c4 = lane & 3;
    const int g8 = lane >> 2;

    const int rowL  = tid >> 1;
    const int khalf = (tid & 1) * 16;

    const uint32_t* Abase = A + (size_t)(m0 + rowL) * DMODEL + khalf;
    const uint32_t* Wbase = W + (size_t)(n0 + rowL) * DMODEL + khalf;
    const uint32_t sAoff = (uint32_t)(rowL * SROW + khalf) * 4u;
    const uint32_t sA0 = smem_u32(As0) + sAoff;
    const uint32_t sW0 = smem_u32(Ws0) + sAoff;
    const uint32_t sA1 = smem_u32(As1) + sAoff;
    const uint32_t sW1 = smem_u32(Ws1) + sAoff;

#define LOAD_CHUNK(c) do {                                                    \
    uint32_t _da = ((c) & 1) ? sA1 : sA0;                                     \
    uint32_t _dw = ((c) & 1) ? sW1 : sW0;                                     \
    const uint32_t* _ga = Abase + (c) * GBK;                                  \
    const uint32_t* _gw = Wbase + (c) * GBK;                                  \
    CP_ASYNC16(_da,      _ga);      CP_ASYNC16(_da + 16, _ga + 4);            \
    CP_ASYNC16(_da + 32, _ga + 8);  CP_ASYNC16(_da + 48, _ga + 12);           \
    CP_ASYNC16(_dw,      _gw);      CP_ASYNC16(_dw + 16, _gw + 4);            \
    CP_ASYNC16(_dw + 32, _gw + 8);  CP_ASYNC16(_dw + 48, _gw + 12);           \
    CP_COMMIT();                                                              \
} while (0)

    float acc[2][8][4];
#pragma unroll
    for (int i = 0; i < 2; ++i)
#pragma unroll
        for (int j = 0; j < 8; ++j)
#pragma unroll
            for (int r = 0; r < 4; ++r) acc[i][j][r] = 0.f;

    LOAD_CHUNK(0);
    LOAD_CHUNK(1);

#pragma unroll 1
    for (int c = 0; c < NCHUNK; ++c) {
        if (c + 1 < NCHUNK) CP_WAIT1(); else CP_WAIT0();
        __syncthreads();

        const uint32_t* Ac = (c & 1) ? As1 : As0;
        const uint32_t* Wc = (c & 1) ? Ws1 : Ws0;

#pragma unroll
        for (int ks = 0; ks < 4; ++ks) {
            const int kk = ks * 8 + c4;
            uint32_t a[2][4];
#pragma unroll
            for (int mt = 0; mt < 2; ++mt) {
                const int rm = m_warp + mt * 16 + g8;
                a[mt][0] = Ac[rm * SROW + kk];
                a[mt][1] = Ac[(rm + 8) * SROW + kk];
                a[mt][2] = Ac[rm * SROW + kk + 4];
                a[mt][3] = Ac[(rm + 8) * SROW + kk + 4];
            }
#pragma unroll
            for (int nt = 0; nt < 8; ++nt) {
                const int rn = n_warp + nt * 8 + g8;
                uint32_t bb0 = Wc[rn * SROW + kk];
                uint32_t bb1 = Wc[rn * SROW + kk + 4];
                mma_tf32(acc[0][nt], a[0], bb0, bb1);
                mma_tf32(acc[1][nt], a[1], bb0, bb1);
            }
        }

        __syncthreads();
        if (c + 2 < NCHUNK) LOAD_CHUNK(c + 2);
    }
#undef LOAD_CHUNK

#pragma unroll
    for (int mt = 0; mt < 2; ++mt) {
        const int row = m0 + m_warp + mt * 16 + g8;
#pragma unroll
        for (int nt = 0; nt < 8; ++nt) {
            const int col = n0 + n_warp + nt * 8 + c4 * 2;
            const float bx = bias[col], by = bias[col + 1];
            if (STORE_BITS) {
                uint32_t* yr0 = (uint32_t*)Y + (size_t)row * DMODEL + col;
                uint32_t* yr1 = (uint32_t*)Y + (size_t)(row + 8) * DMODEL + col;
                uint2 r0, r1;
                r0.x = f2tf32((acc[mt][nt][0] + bx) * scale);
                r0.y = f2tf32((acc[mt][nt][1] + by) * scale);
                r1.x = f2tf32((acc[mt][nt][2] + bx) * scale);
                r1.y = f2tf32((acc[mt][nt][3] + by) * scale);
                *(uint2*)yr0 = r0;
                *(uint2*)yr1 = r1;
            } else {
                float* yr0 = (float*)Y + (size_t)row * DMODEL + col;
                float* yr1 = (float*)Y + (size_t)(row + 8) * DMODEL + col;
                *(float2*)yr0 = make_float2(acc[mt][nt][0] + bx, acc[mt][nt][1] + by);
                *(float2*)yr1 = make_float2(acc[mt][nt][2] + bx, acc[mt][nt][3] + by);
            }
        }
    }
}

// ============================================================================
// Tensor-core causal flash attention (tf32 mma.sync), bit-operand version.
// Q/K/V arrive as tf32 bits (Q pre-scaled by 0.125); ctx written as bits.
// ============================================================================
#define ABK 32
#define KSTR 68
#define VSTR 36
#define PSTR 36
#define ATTN_SMEM (13568 * 4)

__global__ __launch_bounds__(256)
void attn_tc_kernel(const uint32_t* __restrict__ Q, const uint32_t* __restrict__ K,
                    const uint32_t* __restrict__ V, uint32_t* __restrict__ ctx)
{
    extern __shared__ uint32_t sm[];
    uint32_t* KsB[2] = { sm, sm + 32 * KSTR };
    uint32_t* VtB[2] = { sm + 2 * 32 * KSTR,
                         sm + 2 * 32 * KSTR + 64 * VSTR };
    uint32_t* Pw = sm + 2 * 32 * KSTR + 2 * 64 * VSTR;

    const int tid  = threadIdx.x;
    const int wid  = tid >> 5;
    const int lane = tid & 31;
    const int g8 = lane >> 2;
    const int c4 = lane & 3;

    const int bq = blockIdx.x;
    const int h  = blockIdx.y;
    const int b  = blockIdx.z;
    const int wq0 = bq * 128 + wid * 16;
    const size_t seqbase = ((size_t)b * TSEQ) * DMODEL + (size_t)h * DK;

    uint32_t* Pme = Pw + wid * 16 * PSTR;

    // ---- Q fragments (already tf32 bits, scale folded upstream) ----
    uint32_t qa[8][4];
    {
        const uint32_t* qlo = Q + seqbase + (size_t)(wq0 + g8) * DMODEL;
        const uint32_t* qhi = qlo + 8 * DMODEL;
#pragma unroll
        for (int ks = 0; ks < 8; ++ks) {
            qa[ks][0] = qlo[8 * ks + c4];
            qa[ks][1] = qhi[8 * ks + c4];
            qa[ks][2] = qlo[8 * ks + c4 + 4];
            qa[ks][3] = qhi[8 * ks + c4 + 4];
        }
    }

    const int ntiles = 4 * bq + 4;

    const int kkey = tid >> 3, kseg = (tid & 7) * 8;
    const int vkey = tid & 31, vseg = (tid >> 5) * 8;
    const uint32_t ks0a = smem_u32(KsB[0]) + (uint32_t)(kkey * KSTR + kseg) * 4u;
    const uint32_t ks1a = smem_u32(KsB[1]) + (uint32_t)(kkey * KSTR + kseg) * 4u;

    {
        const uint32_t* kr = K + seqbase + (size_t)kkey * DMODEL + kseg;
        CP_ASYNC16(ks0a, kr); CP_ASYNC16(ks0a + 16, kr + 4);
        CP_COMMIT();
    }
    {
        const uint32_t* vr = V + seqbase + (size_t)vkey * DMODEL + vseg;
        uint4 a = *(const uint4*)vr, c = *(const uint4*)(vr + 4);
        uint32_t* Vn = VtB[0];
        Vn[(vseg + 0) * VSTR + vkey] = a.x;
        Vn[(vseg + 1) * VSTR + vkey] = a.y;
        Vn[(vseg + 2) * VSTR + vkey] = a.z;
        Vn[(vseg + 3) * VSTR + vkey] = a.w;
        Vn[(vseg + 4) * VSTR + vkey] = c.x;
        Vn[(vseg + 5) * VSTR + vkey] = c.y;
        Vn[(vseg + 6) * VSTR + vkey] = c.z;
        Vn[(vseg + 7) * VSTR + vkey] = c.w;
    }
    uint4 va, vb;
    {
        const uint32_t* kr = K + seqbase + (size_t)(ABK + kkey) * DMODEL + kseg;
        CP_ASYNC16(ks1a, kr); CP_ASYNC16(ks1a + 16, kr + 4);
        CP_COMMIT();
        const uint32_t* vr = V + seqbase + (size_t)(ABK + vkey) * DMODEL + vseg;
        va = *(const uint4*)vr; vb = *(const uint4*)(vr + 4);
    }
    CP_WAIT1();
    __syncthreads();

    float m0 = -1e30f, m1 = -1e30f, l0 = 0.f, l1 = 0.f;
    float o[8][4];
#pragma unroll
    for (int nf = 0; nf < 8; ++nf)
#pragma unroll
        for (int r = 0; r < 4; ++r) o[nf][r] = 0.f;

    const int rlo = wq0 + g8, rhi = rlo + 8;

#pragma unroll 1
    for (int it = 0; it < ntiles; ++it) {
        const int k0 = it * ABK;
        const uint32_t* Kc = KsB[it & 1];
        const uint32_t* Vc = VtB[it & 1];

        uint4 na, nb;
        const bool have2 = (it + 2 < ntiles);
        if (have2) {
            const uint32_t* vr = V + seqbase + (size_t)((it + 2) * ABK + vkey) * DMODEL + vseg;
            na = *(const uint4*)vr; nb = *(const uint4*)(vr + 4);
        }

        if (k0 <= wq0 + 15) {
            float s[4][4];
#pragma unroll
            for (int nf = 0; nf < 4; ++nf)
#pragma unroll
                for (int r = 0; r < 4; ++r) s[nf][r] = 0.f;
#pragma unroll
            for (int ks = 0; ks < 8; ++ks) {
#pragma unroll
                for (int nf = 0; nf < 4; ++nf) {
                    const uint32_t* kp = Kc + (nf * 8 + g8) * KSTR + ks * 8 + c4;
                    mma_tf32(s[nf], qa[ks], kp[0], kp[4]);
                }
            }

            if (k0 + ABK - 1 > wq0) {
#pragma unroll
                for (int nf = 0; nf < 4; ++nf) {
                    const int kg = k0 + nf * 8 + 2 * c4;
                    if (kg     > rlo) s[nf][0] = -1e30f;
                    if (kg + 1 > rlo) s[nf][1] = -1e30f;
                    if (kg     > rhi) s[nf][2] = -1e30f;
                    if (kg + 1 > rhi) s[nf][3] = -1e30f;
                }
            }

            float tl = -1e30f, th = -1e30f;
#pragma unroll
            for (int nf = 0; nf < 4; ++nf) {
                tl = fmaxf(tl, fmaxf(s[nf][0], s[nf][1]));
                th = fmaxf(th, fmaxf(s[nf][2], s[nf][3]));
            }
            tl = fmaxf(tl, __shfl_xor_sync(0xffffffffu, tl, 1));
            tl = fmaxf(tl, __shfl_xor_sync(0xffffffffu, tl, 2));
            th = fmaxf(th, __shfl_xor_sync(0xffffffffu, th, 1));
            th = fmaxf(th, __shfl_xor_sync(0xffffffffu, th, 2));

            const float mn0 = fmaxf(m0, tl), mn1 = fmaxf(m1, th);
            const float cr0 = __expf(m0 - mn0), cr1 = __expf(m1 - mn1);
            float sl = 0.f, sh = 0.f;
#pragma unroll
            for (int nf = 0; nf < 4; ++nf) {
                float p0 = __expf(s[nf][0] - mn0);
                float p1 = __expf(s[nf][1] - mn0);
                float p2 = __expf(s[nf][2] - mn1);
                float p3 = __expf(s[nf][3] - mn1);
                sl += p0 + p1; sh += p2 + p3;
                Pme[g8 * PSTR + nf * 8 + 2 * c4]           = f2tf32(p0);
                Pme[g8 * PSTR + nf * 8 + 2 * c4 + 1]       = f2tf32(p1);
                Pme[(g8 + 8) * PSTR + nf * 8 + 2 * c4]     = f2tf32(p2);
                Pme[(g8 + 8) * PSTR + nf * 8 + 2 * c4 + 1] = f2tf32(p3);
            }
            sl += __shfl_xor_sync(0xffffffffu, sl, 1);
            sl += __shfl_xor_sync(0xffffffffu, sl, 2);
            sh += __shfl_xor_sync(0xffffffffu, sh, 1);
            sh += __shfl_xor_sync(0xffffffffu, sh, 2);
            l0 = l0 * cr0 + sl;  l1 = l1 * cr1 + sh;
            m0 = mn0;  m1 = mn1;
#pragma unroll
            for (int nf = 0; nf < 8; ++nf) {
                o[nf][0] *= cr0; o[nf][1] *= cr0;
                o[nf][2] *= cr1; o[nf][3] *= cr1;
            }
            __syncwarp();

#pragma unroll
            for (int ks = 0; ks < 4; ++ks) {
                uint32_t a[4];
                a[0] = Pme[g8 * PSTR + ks * 8 + c4];
                a[1] = Pme[(g8 + 8) * PSTR + ks * 8 + c4];
                a[2] = Pme[g8 * PSTR + ks * 8 + c4 + 4];
                a[3] = Pme[(g8 + 8) * PSTR + ks * 8 + c4 + 4];
#pragma unroll
                for (int nf = 0; nf < 8; ++nf) {
                    uint32_t bb0 = Vc[(nf * 8 + g8) * VSTR + ks * 8 + c4];
                    uint32_t bb1 = Vc[(nf * 8 + g8) * VSTR + ks * 8 + c4 + 4];
                    mma_tf32(o[nf], a, bb0, bb1);
                }
            }
        }

        if (it + 1 < ntiles) {
            CP_WAIT0();
            __syncthreads();
            uint32_t* Vn = VtB[(it + 1) & 1];
            Vn[(vseg + 0) * VSTR + vkey] = va.x;
            Vn[(vseg + 1) * VSTR + vkey] = va.y;
            Vn[(vseg + 2) * VSTR + vkey] = va.z;
            Vn[(vseg + 3) * VSTR + vkey] = va.w;
            Vn[(vseg + 4) * VSTR + vkey] = vb.x;
            Vn[(vseg + 5) * VSTR + vkey] = vb.y;
            Vn[(vseg + 6) * VSTR + vkey] = vb.z;
            Vn[(vseg + 7) * VSTR + vkey] = vb.w;
            if (have2) {
                const uint32_t* kr = K + seqbase + (size_t)((it + 2) * ABK + kkey) * DMODEL + kseg;
                const uint32_t dst = (it & 1) ? ks1a : ks0a;
                CP_ASYNC16(dst, kr); CP_ASYNC16(dst + 16, kr + 4);
                CP_COMMIT();
                va = na; vb = nb;
            }
            __syncthreads();
        }
    }

    // ---- epilogue: write ctx as tf32 bits ----
    const float inv0 = 1.f / l0, inv1 = 1.f / l1;
    uint32_t* olo = ctx + seqbase + (size_t)rlo * DMODEL;
    uint32_t* ohi = ctx + seqbase + (size_t)rhi * DMODEL;
#pragma unroll
    for (int nf = 0; nf < 8; ++nf) {
        const int col = nf * 8 + 2 * c4;
        uint2 r0, r1;
        r0.x = f2tf32(o[nf][0] * inv0); r0.y = f2tf32(o[nf][1] * inv0);
        r1.x = f2tf32(o[nf][2] * inv1); r1.y = f2tf32(o[nf][3] * inv1);
        *(uint2*)(olo + col) = r0;
        *(uint2*)(ohi + col) = r1;
    }
}

// ============================================================================
// launch
// ============================================================================
extern "C" void kernel_launch(void* const* d_in, const int* in_sizes, int n_in,
                              void* d_out, int out_size)
{
    const float* x  = (const float*)d_in[0];
    const float* Wq = (const float*)d_in[1];
    const float* bq = (const float*)d_in[2];
    const float* Wk = (const float*)d_in[3];
    const float* bk = (const float*)d_in[4];
    const float* Wv = (const float*)d_in[5];
    const float* bv = (const float*)d_in[6];
    const float* Wo = (const float*)d_in[7];
    const float* bo = (const float*)d_in[8];
    float* out = (float*)d_out;

    uint32_t *xb, *wb, *qp, *kp, *vp, *cp;
    cudaGetSymbolAddress((void**)&xb, g_xb);
    cudaGetSymbolAddress((void**)&wb, g_Wb);
    cudaGetSymbolAddress((void**)&qp, g_Q);
    cudaGetSymbolAddress((void**)&kp, g_K);
    cudaGetSymbolAddress((void**)&vp, g_V);
    cudaGetSymbolAddress((void**)&cp, g_ctx);

    cudaFuncSetAttribute(gemm_tc_kernel<1>,
                         cudaFuncAttributeMaxDynamicSharedMemorySize, GEMM_SMEM);
    cudaFuncSetAttribute(gemm_tc_kernel<0>,
                         cudaFuncAttributeMaxDynamicSharedMemorySize, GEMM_SMEM);
    cudaFuncSetAttribute(attn_tc_kernel,
                         cudaFuncAttributeMaxDynamicSharedMemorySize, ATTN_SMEM);

    // 1) pre-convert x + all weights to tf32 bits
    cvt_tf32_kernel<<<(XN4 + 4 * WN4) / 256, 256>>>(
        (const float4*)x, (const float4*)Wq, (const float4*)Wk,
        (const float4*)Wv, (const float4*)Wo, (uint4*)xb, (uint4*)wb);

    // 2) fused QKV projections -> tf32 bits (Q scaled by 1/sqrt(dk))
    dim3 qkv_grid(DMODEL / 128, MTOK / 128, 3);   // (8, 32, 3)
    gemm_tc_kernel<1><<<qkv_grid, 256, GEMM_SMEM>>>(
        xb, wb, wb + WN4 * 4, wb + 2 * (size_t)WN4 * 4,
        bq, bk, bv, qp, kp, vp, 0.125f, 1.f, 1.f);

    // 3) attention
    dim3 agrid(TSEQ / 128, NHEADS, BDIM);         // (16, 16, 2)
    attn_tc_kernel<<<agrid, 256, ATTN_SMEM>>>(qp, kp, vp, cp);

    // 4) output projection -> fp32 d_out
    dim3 o_grid(DMODEL / 128, MTOK / 128, 1);
    gemm_tc_kernel<0><<<o_grid, 256, GEMM_SMEM>>>(
        cp, wb + 3 * (size_t)WN4 * 4, wb, wb,
        bo, bo, bo, out, out, out, 1.f, 1.f, 1.f);
}

// round 12
// speedup vs baseline: 2.0502x; 1.8556x over previous
#include <cuda_runtime.h>
#include <cuda_fp16.h>
#include <cstdint>
#include <math.h>

#define BDIM 2
#define TSEQ 2048
#define DMODEL 1024
#define DM32 (DMODEL / 2)     // row stride in u32 (packed half2)
#define NHEADS 16
#define DK 64
#define MTOK (BDIM * TSEQ)    // 4096

// -------- scratch (device globals; packed fp16 pairs as u32) --------
__device__ uint32_t g_xh[MTOK * DM32];            // x as fp16
__device__ uint32_t g_Wh[4 * DMODEL * DM32];      // Wq,Wk,Wv,Wo as fp16
__device__ uint32_t g_Q[MTOK * DM32];             // Q*0.125 fp16
__device__ uint32_t g_K[MTOK * DM32];
__device__ uint32_t g_V[MTOK * DM32];
__device__ uint32_t g_ctx[MTOK * DM32];           // attention out fp16

// ============================================================================
// helpers
// ============================================================================
__device__ __forceinline__ uint32_t smem_u32(const void* p) {
    uint32_t a;
    asm("{ .reg .u64 t; cvta.to.shared.u64 t, %1; cvt.u32.u64 %0, t; }" : "=r"(a) : "l"(p));
    return a;
}

// pack two fp32 -> {lo, hi} fp16x2 (cvt d, hi, lo)
__device__ __forceinline__ uint32_t pack_h2(float lo, float hi) {
    uint32_t r;
    asm("cvt.rn.f16x2.f32 %0, %1, %2;" : "=r"(r) : "f"(hi), "f"(lo));
    return r;
}

__device__ __forceinline__ void mma_f16(float* d, const uint32_t* a,
                                        uint32_t b0, uint32_t b1) {
    asm volatile(
        "mma.sync.aligned.m16n8k16.row.col.f32.f16.f16.f32 "
        "{%0,%1,%2,%3}, {%4,%5,%6,%7}, {%8,%9}, {%0,%1,%2,%3};"
        : "+f"(d[0]), "+f"(d[1]), "+f"(d[2]), "+f"(d[3])
        : "r"(a[0]), "r"(a[1]), "r"(a[2]), "r"(a[3]), "r"(b0), "r"(b1));
}

#define CP_ASYNC16(dst, src) \
    asm volatile("cp.async.cg.shared.global [%0], [%1], 16;" \
                 :: "r"((uint32_t)(dst)), "l"(src) : "memory")
#define CP_COMMIT() asm volatile("cp.async.commit_group;" ::: "memory")
#define CP_WAIT1()  asm volatile("cp.async.wait_group 1;" ::: "memory")
#define CP_WAIT0()  asm volatile("cp.async.wait_group 0;" ::: "memory")

// ============================================================================
// Pre-convert fp32 -> packed fp16: x (1M float4) + 4 weights (4 x 256K float4)
// ============================================================================
#define XN4   (MTOK * DMODEL / 4)        // 1048576
#define WN4   (DMODEL * DMODEL / 4)      // 262144

__global__ __launch_bounds__(256)
void cvt_h_kernel(const float4* __restrict__ x,
                  const float4* __restrict__ wq, const float4* __restrict__ wk,
                  const float4* __restrict__ wv, const float4* __restrict__ wo,
                  uint2* __restrict__ xh, uint2* __restrict__ wh)
{
    const int i = blockIdx.x * 256 + threadIdx.x;
    const float4* src;
    uint2* dst;
    if (i < XN4) {
        src = x + i; dst = xh + i;
    } else {
        const int j = i - XN4;
        const int w = j >> 18;
        const int off = j & (WN4 - 1);
        const float4* ws[4] = { wq, wk, wv, wo };
        src = ws[w] + off;
        dst = wh + (size_t)w * WN4 + off;
    }
    float4 v = *src;
    uint2 u;
    u.x = pack_h2(v.x, v.y);
    u.y = pack_h2(v.z, v.w);
    *dst = u;
}

// ============================================================================
// fp16 mma.sync GEMM: Y = A * W^T + bias. A,W packed fp16 (u32 = half2).
// CTA 128x128, BK=64 halves, 256 thr (8 warps 4x2), warp tile 32x64,
// double-buffered cp.async. STORE_HALF=1 -> Y packed fp16 of (acc+b)*scale.
// ============================================================================
#define NCHUNK 16                    // 1024 / 64
#define SR32 36                      // u32 row stride (32 data + 4 pad)
#define TILE_U (128 * SR32)          // 4608 u32 per array per stage
#define GEMM_SMEM (4 * TILE_U * 4)   // 73728 bytes

template<int STORE_HALF>
__global__ __launch_bounds__(256)
void gemm_h_kernel(const uint32_t* __restrict__ A,
                   const uint32_t* __restrict__ W0, const uint32_t* __restrict__ W1,
                   const uint32_t* __restrict__ W2,
                   const float* __restrict__ b0, const float* __restrict__ b1,
                   const float* __restrict__ b2,
                   void* __restrict__ Y0, void* __restrict__ Y1,
                   void* __restrict__ Y2,
                   float s0, float s1, float s2)
{
    extern __shared__ uint32_t smem[];
    uint32_t* As0 = smem;
    uint32_t* Ws0 = As0 + TILE_U;
    uint32_t* As1 = Ws0 + TILE_U;
    uint32_t* Ws1 = As1 + TILE_U;

    const uint32_t* W = W0; const float* bias = b0; void* Y = Y0; float scale = s0;
    if (blockIdx.z == 1) { W = W1; bias = b1; Y = Y1; scale = s1; }
    else if (blockIdx.z == 2) { W = W2; bias = b2; Y = Y2; scale = s2; }

    const int tid  = threadIdx.x;
    const int wid  = tid >> 5;
    const int lane = tid & 31;
    const int m0 = blockIdx.y * 128;
    const int n0 = blockIdx.x * 128;

    const int m_warp = (wid & 3) * 32;
    const int n_warp = (wid >> 2) * 64;
    const int c4 = lane & 3;
    const int g8 = lane >> 2;

    // loader: row = tid>>1, half-of-row = (tid&1)*16 u32 (64B); 4 cp16 each arr
    const int rowL = tid >> 1;
    const int hof  = (tid & 1) * 16;     // u32 offset within 32-u32 row

    const uint32_t* Abase = A + (size_t)(m0 + rowL) * DM32 + hof;
    const uint32_t* Wbase = W + (size_t)(n0 + rowL) * DM32 + hof;
    const uint32_t soff = (uint32_t)(rowL * SR32 + hof) * 4u;
    const uint32_t sA0 = smem_u32(As0) + soff;
    const uint32_t sW0 = smem_u32(Ws0) + soff;
    const uint32_t sA1 = smem_u32(As1) + soff;
    const uint32_t sW1 = smem_u32(Ws1) + soff;

#define LOAD_CHUNK(c) do {                                                    \
    uint32_t _da = ((c) & 1) ? sA1 : sA0;                                     \
    uint32_t _dw = ((c) & 1) ? sW1 : sW0;                                     \
    const uint32_t* _ga = Abase + (c) * 32;                                   \
    const uint32_t* _gw = Wbase + (c) * 32;                                   \
    CP_ASYNC16(_da,      _ga);      CP_ASYNC16(_da + 16, _ga + 4);            \
    CP_ASYNC16(_da + 32, _ga + 8);  CP_ASYNC16(_da + 48, _ga + 12);           \
    CP_ASYNC16(_dw,      _gw);      CP_ASYNC16(_dw + 16, _gw + 4);            \
    CP_ASYNC16(_dw + 32, _gw + 8);  CP_ASYNC16(_dw + 48, _gw + 12);           \
    CP_COMMIT();                                                              \
} while (0)

    float acc[2][8][4];
#pragma unroll
    for (int i = 0; i < 2; ++i)
#pragma unroll
        for (int j = 0; j < 8; ++j)
#pragma unroll
            for (int r = 0; r < 4; ++r) acc[i][j][r] = 0.f;

    LOAD_CHUNK(0);
    LOAD_CHUNK(1);

#pragma unroll 1
    for (int c = 0; c < NCHUNK; ++c) {
        if (c + 1 < NCHUNK) CP_WAIT1(); else CP_WAIT0();
        __syncthreads();

        const uint32_t* Ac = (c & 1) ? As1 : As0;
        const uint32_t* Wc = (c & 1) ? Ws1 : Ws0;

#pragma unroll
        for (int ks = 0; ks < 4; ++ks) {             // k16 steps within 64 halves
            const int kk = ks * 8 + c4;
            uint32_t a[2][4];
#pragma unroll
            for (int mt = 0; mt < 2; ++mt) {
                const int rm = m_warp + mt * 16 + g8;
                a[mt][0] = Ac[rm * SR32 + kk];
                a[mt][1] = Ac[(rm + 8) * SR32 + kk];
                a[mt][2] = Ac[rm * SR32 + kk + 4];
                a[mt][3] = Ac[(rm + 8) * SR32 + kk + 4];
            }
#pragma unroll
            for (int nt = 0; nt < 8; ++nt) {
                const int rn = n_warp + nt * 8 + g8;
                uint32_t bb0 = Wc[rn * SR32 + kk];
                uint32_t bb1 = Wc[rn * SR32 + kk + 4];
                mma_f16(acc[0][nt], a[0], bb0, bb1);
                mma_f16(acc[1][nt], a[1], bb0, bb1);
            }
        }

        __syncthreads();
        if (c + 2 < NCHUNK) LOAD_CHUNK(c + 2);
    }
#undef LOAD_CHUNK

#pragma unroll
    for (int mt = 0; mt < 2; ++mt) {
        const int row = m0 + m_warp + mt * 16 + g8;
#pragma unroll
        for (int nt = 0; nt < 8; ++nt) {
            const int col = n0 + n_warp + nt * 8 + c4 * 2;
            const float bx = bias[col], by = bias[col + 1];
            if (STORE_HALF) {
                uint32_t* y0 = (uint32_t*)Y + (size_t)row * DM32 + col / 2;
                uint32_t* y1 = (uint32_t*)Y + (size_t)(row + 8) * DM32 + col / 2;
                *y0 = pack_h2((acc[mt][nt][0] + bx) * scale,
                              (acc[mt][nt][1] + by) * scale);
                *y1 = pack_h2((acc[mt][nt][2] + bx) * scale,
                              (acc[mt][nt][3] + by) * scale);
            } else {
                float* y0 = (float*)Y + (size_t)row * DMODEL + col;
                float* y1 = (float*)Y + (size_t)(row + 8) * DMODEL + col;
                *(float2*)y0 = make_float2(acc[mt][nt][0] + bx, acc[mt][nt][1] + by);
                *(float2*)y1 = make_float2(acc[mt][nt][2] + bx, acc[mt][nt][3] + by);
            }
        }
    }
}

// ============================================================================
// fp16 tensor-core causal flash attention.
// 8 warps x 16 q-rows; Bk=32 keys/tile; dk=64. K smem u32[32][36] (k-pairs),
// Vt smem u32[64][20] (key-pairs, transposed). P stays in registers:
// softmax C-frags pack directly into PV A-frags (no smem round trip).
// ============================================================================
#define KST 36
#define VST 20

__global__ __launch_bounds__(256)
void attn_h_kernel(const uint32_t* __restrict__ Q, const uint32_t* __restrict__ K,
                   const uint32_t* __restrict__ V, uint32_t* __restrict__ ctx)
{
    __shared__ uint32_t sK[2][32 * KST];
    __shared__ uint32_t sV[2][64 * VST];

    const int tid  = threadIdx.x;
    const int wid  = tid >> 5;
    const int lane = tid & 31;
    const int g8 = lane >> 2;
    const int c4 = lane & 3;

    const int bq = blockIdx.x;
    const int h  = blockIdx.y;
    const int b  = blockIdx.z;
    const int wq0 = bq * 128 + wid * 16;
    const size_t base32 = ((size_t)b * TSEQ) * DM32 + (size_t)h * (DK / 2);

    // ---- Q fragments (fp16 pairs, 0.125 pre-folded): 4 ksteps x 4 regs ----
    uint32_t qa[4][4];
    {
        const uint32_t* qlo = Q + base32 + (size_t)(wq0 + g8) * DM32;
        const uint32_t* qhi = qlo + 8 * DM32;
#pragma unroll
        for (int ks = 0; ks < 4; ++ks) {
            qa[ks][0] = qlo[8 * ks + c4];
            qa[ks][1] = qhi[8 * ks + c4];
            qa[ks][2] = qlo[8 * ks + c4 + 4];
            qa[ks][3] = qhi[8 * ks + c4 + 4];
        }
    }

    const int ntiles = 4 * bq + 4;

    // loader mappings
    const int kkey = tid >> 3, kx = (tid & 7) * 4;     // K: row, 4-u32 seg
    const int vkp  = tid & 15, vds = tid >> 4;         // V: key-pair, 4-d seg
    const uint32_t ka0 = smem_u32(sK[0]) + (uint32_t)(kkey * KST + kx) * 4u;
    const uint32_t ka1 = smem_u32(sK[1]) + (uint32_t)(kkey * KST + kx) * 4u;

#define STORE_VT(bufidx, u0, u1) do {                                         \
    uint32_t* Vn = sV[bufidx] + vkp;                                          \
    __half2 a0 = *(__half2*)&(u0).x, a1 = *(__half2*)&(u0).y;                 \
    __half2 b0v = *(__half2*)&(u1).x, b1v = *(__half2*)&(u1).y;               \
    Vn[(4 * vds + 0) * VST] = __byte_perm((u0).x, (u1).x, 0x5410);            \
    Vn[(4 * vds + 1) * VST] = __byte_perm((u0).x, (u1).x, 0x7632);            \
    Vn[(4 * vds + 2) * VST] = __byte_perm((u0).y, (u1).y, 0x5410);            \
    Vn[(4 * vds + 3) * VST] = __byte_perm((u0).y, (u1).y, 0x7632);            \
    (void)a0; (void)a1; (void)b0v; (void)b1v;                                 \
} while (0)

    // ---- prologue ----
    {
        const uint32_t* kr = K + base32 + (size_t)kkey * DM32 + kx;
        CP_ASYNC16(ka0, kr);
        CP_COMMIT();
    }
    {
        const uint32_t* v0 = V + base32 + (size_t)(2 * vkp) * DM32 + 2 * vds;
        const uint32_t* v1 = v0 + DM32;
        uint2 u0 = *(const uint2*)v0, u1 = *(const uint2*)v1;
        STORE_VT(0, u0, u1);
    }
    uint2 va, vb;   // V(it+1) staged in regs
    {
        const uint32_t* kr = K + base32 + (size_t)(32 + kkey) * DM32 + kx;
        CP_ASYNC16(ka1, kr);
        CP_COMMIT();
        const uint32_t* v0 = V + base32 + (size_t)(32 + 2 * vkp) * DM32 + 2 * vds;
        va = *(const uint2*)v0; vb = *(const uint2*)(v0 + DM32);
    }
    CP_WAIT1();
    __syncthreads();

    float m0 = -1e30f, m1 = -1e30f, l0 = 0.f, l1 = 0.f;
    float o[8][4];
#pragma unroll
    for (int nf = 0; nf < 8; ++nf)
#pragma unroll
        for (int r = 0; r < 4; ++r) o[nf][r] = 0.f;

    const int rlo = wq0 + g8, rhi = rlo + 8;

#pragma unroll 1
    for (int it = 0; it < ntiles; ++it) {
        const int k0 = it * 32;
        const uint32_t* Kc = sK[it & 1];
        const uint32_t* Vc = sV[it & 1];

        uint2 na, nb;
        const bool have2 = (it + 2 < ntiles);
        if (have2) {
            const uint32_t* v0 = V + base32
                + (size_t)((it + 2) * 32 + 2 * vkp) * DM32 + 2 * vds;
            na = *(const uint2*)v0; nb = *(const uint2*)(v0 + DM32);
        }

        if (k0 <= wq0 + 15) {
            // ---- S = Q K^T : 4 ksteps x 4 key-frags ----
            float s[4][4];
#pragma unroll
            for (int nf = 0; nf < 4; ++nf)
#pragma unroll
                for (int r = 0; r < 4; ++r) s[nf][r] = 0.f;
#pragma unroll
            for (int ks = 0; ks < 4; ++ks) {
#pragma unroll
                for (int nf = 0; nf < 4; ++nf) {
                    const uint32_t* kp = Kc + (nf * 8 + g8) * KST + ks * 8 + c4;
                    mma_f16(s[nf], qa[ks], kp[0], kp[4]);
                }
            }

            // ---- causal mask (diagonal tiles only) ----
            if (k0 + 31 > wq0) {
#pragma unroll
                for (int nf = 0; nf < 4; ++nf) {
                    const int kg = k0 + nf * 8 + 2 * c4;
                    if (kg     > rlo) s[nf][0] = -1e30f;
                    if (kg + 1 > rlo) s[nf][1] = -1e30f;
                    if (kg     > rhi) s[nf][2] = -1e30f;
                    if (kg + 1 > rhi) s[nf][3] = -1e30f;
                }
            }

            // ---- online softmax (P stays in registers) ----
            float tl = -1e30f, th = -1e30f;
#pragma unroll
            for (int nf = 0; nf < 4; ++nf) {
                tl = fmaxf(tl, fmaxf(s[nf][0], s[nf][1]));
                th = fmaxf(th, fmaxf(s[nf][2], s[nf][3]));
            }
            tl = fmaxf(tl, __shfl_xor_sync(0xffffffffu, tl, 1));
            tl = fmaxf(tl, __shfl_xor_sync(0xffffffffu, tl, 2));
            th = fmaxf(th, __shfl_xor_sync(0xffffffffu, th, 1));
            th = fmaxf(th, __shfl_xor_sync(0xffffffffu, th, 2));

            const float mn0 = fmaxf(m0, tl), mn1 = fmaxf(m1, th);
            const float cr0 = __expf(m0 - mn0), cr1 = __expf(m1 - mn1);
            float e[4][4];
            float sl = 0.f, sh = 0.f;
#pragma unroll
            for (int nf = 0; nf < 4; ++nf) {
                e[nf][0] = __expf(s[nf][0] - mn0);
                e[nf][1] = __expf(s[nf][1] - mn0);
                e[nf][2] = __expf(s[nf][2] - mn1);
                e[nf][3] = __expf(s[nf][3] - mn1);
                sl += e[nf][0] + e[nf][1];
                sh += e[nf][2] + e[nf][3];
            }
            sl += __shfl_xor_sync(0xffffffffu, sl, 1);
            sl += __shfl_xor_sync(0xffffffffu, sl, 2);
            sh += __shfl_xor_sync(0xffffffffu, sh, 1);
            sh += __shfl_xor_sync(0xffffffffu, sh, 2);
            l0 = l0 * cr0 + sl;  l1 = l1 * cr1 + sh;
            m0 = mn0;  m1 = mn1;
#pragma unroll
            for (int nf = 0; nf < 8; ++nf) {
                o[nf][0] *= cr0; o[nf][1] *= cr0;
                o[nf][2] *= cr1; o[nf][3] *= cr1;
            }

            // ---- O += P V : P A-frags packed straight from e ----
#pragma unroll
            for (int ks = 0; ks < 2; ++ks) {          // k16 over 32 keys
                uint32_t a[4];
                a[0] = pack_h2(e[2 * ks][0],     e[2 * ks][1]);
                a[1] = pack_h2(e[2 * ks][2],     e[2 * ks][3]);
                a[2] = pack_h2(e[2 * ks + 1][0], e[2 * ks + 1][1]);
                a[3] = pack_h2(e[2 * ks + 1][2], e[2 * ks + 1][3]);
#pragma unroll
                for (int nf = 0; nf < 8; ++nf) {
                    const uint32_t* vp = Vc + (nf * 8 + g8) * VST + ks * 8 + c4;
                    mma_f16(o[nf], a, vp[0], vp[4]);
                }
            }
        }

        // ---- pipeline advance ----
        if (it + 1 < ntiles) {
            CP_WAIT0();
            __syncthreads();
            STORE_VT((it + 1) & 1, va, vb);
            if (have2) {
                const uint32_t* kr = K + base32
                    + (size_t)((it + 2) * 32 + kkey) * DM32 + kx;
                CP_ASYNC16((it & 1) ? ka1 : ka0, kr);
                CP_COMMIT();
                va = na; vb = nb;
            }
            __syncthreads();
        }
    }
#undef STORE_VT

    // ---- epilogue: ctx as packed fp16 ----
    const float inv0 = 1.f / l0, inv1 = 1.f / l1;
    uint32_t* olo = ctx + base32 + (size_t)rlo * DM32;
    uint32_t* ohi = ctx + base32 + (size_t)rhi * DM32;
#pragma unroll
    for (int nf = 0; nf < 8; ++nf) {
        olo[nf * 4 + c4] = pack_h2(o[nf][0] * inv0, o[nf][1] * inv0);
        ohi[nf * 4 + c4] = pack_h2(o[nf][2] * inv1, o[nf][3] * inv1);
    }
}

// ============================================================================
// launch
// ============================================================================
extern "C" void kernel_launch(void* const* d_in, const int* in_sizes, int n_in,
                              void* d_out, int out_size)
{
    const float* x  = (const float*)d_in[0];
    const float* Wq = (const float*)d_in[1];
    const float* bq = (const float*)d_in[2];
    const float* Wk = (const float*)d_in[3];
    const float* bk = (const float*)d_in[4];
    const float* Wv = (const float*)d_in[5];
    const float* bv = (const float*)d_in[6];
    const float* Wo = (const float*)d_in[7];
    const float* bo = (const float*)d_in[8];
    float* out = (float*)d_out;

    uint32_t *xh, *wh, *qp, *kp, *vp, *cp;
    cudaGetSymbolAddress((void**)&xh, g_xh);
    cudaGetSymbolAddress((void**)&wh, g_Wh);
    cudaGetSymbolAddress((void**)&qp, g_Q);
    cudaGetSymbolAddress((void**)&kp, g_K);
    cudaGetSymbolAddress((void**)&vp, g_V);
    cudaGetSymbolAddress((void**)&cp, g_ctx);

    cudaFuncSetAttribute(gemm_h_kernel<1>,
                         cudaFuncAttributeMaxDynamicSharedMemorySize, GEMM_SMEM);
    cudaFuncSetAttribute(gemm_h_kernel<0>,
                         cudaFuncAttributeMaxDynamicSharedMemorySize, GEMM_SMEM);

    // 1) pre-convert x + weights to packed fp16
    cvt_h_kernel<<<(XN4 + 4 * WN4) / 256, 256>>>(
        (const float4*)x, (const float4*)Wq, (const float4*)Wk,
        (const float4*)Wv, (const float4*)Wo, (uint2*)xh, (uint2*)wh);

    // 2) fused QKV projections (Q scaled by 1/sqrt(dk))
    const size_t W32 = (size_t)DMODEL * DM32;     // u32 per weight matrix
    dim3 qkv_grid(DMODEL / 128, MTOK / 128, 3);   // (8, 32, 3)
    gemm_h_kernel<1><<<qkv_grid, 256, GEMM_SMEM>>>(
        xh, wh, wh + W32, wh + 2 * W32,
        bq, bk, bv, qp, kp, vp, 0.125f, 1.f, 1.f);

    // 3) attention
    dim3 agrid(TSEQ / 128, NHEADS, BDIM);         // (16, 16, 2)
    attn_h_kernel<<<agrid, 256>>>(qp, kp, vp, cp);

    // 4) output projection -> fp32 d_out
    dim3 o_grid(DMODEL / 128, MTOK / 128, 1);
    gemm_h_kernel<0><<<o_grid, 256, GEMM_SMEM>>>(
        cp, wh + 3 * W32, wh, wh,
        bo, bo, bo, out, out, out, 1.f, 1.f, 1.f);
}

// round 14
// speedup vs baseline: 2.2308x; 1.0881x over previous
#include <cuda_runtime.h>
#include <cuda_fp16.h>
#include <cstdint>
#include <math.h>

#define BDIM 2
#define TSEQ 2048
#define DMODEL 1024
#define DM32 (DMODEL / 2)     // row stride in u32 (packed half2)
#define NHEADS 16
#define DK 64
#define MTOK (BDIM * TSEQ)    // 4096

// -------- scratch (device globals; packed fp16 pairs as u32) --------
__device__ uint32_t g_xh[MTOK * DM32];
__device__ uint32_t g_Wh[4 * DMODEL * DM32];
__device__ uint32_t g_Q[MTOK * DM32];
__device__ uint32_t g_K[MTOK * DM32];
__device__ uint32_t g_V[MTOK * DM32];
__device__ uint32_t g_ctx[MTOK * DM32];

// ============================================================================
// helpers
// ============================================================================
__device__ __forceinline__ uint32_t smem_u32(const void* p) {
    uint32_t a;
    asm("{ .reg .u64 t; cvta.to.shared.u64 t, %1; cvt.u32.u64 %0, t; }" : "=r"(a) : "l"(p));
    return a;
}

__device__ __forceinline__ uint32_t pack_h2(float lo, float hi) {
    uint32_t r;
    asm("cvt.rn.f16x2.f32 %0, %1, %2;" : "=r"(r) : "f"(hi), "f"(lo));
    return r;
}

__device__ __forceinline__ void mma_f16(float* d, const uint32_t* a,
                                        uint32_t b0, uint32_t b1) {
    asm volatile(
        "mma.sync.aligned.m16n8k16.row.col.f32.f16.f16.f32 "
        "{%0,%1,%2,%3}, {%4,%5,%6,%7}, {%8,%9}, {%0,%1,%2,%3};"
        : "+f"(d[0]), "+f"(d[1]), "+f"(d[2]), "+f"(d[3])
        : "r"(a[0]), "r"(a[1]), "r"(a[2]), "r"(a[3]), "r"(b0), "r"(b1));
}

#define LDSM4(r0, r1, r2, r3, addr) \
    asm volatile("ldmatrix.sync.aligned.m8n8.x4.shared.b16 {%0,%1,%2,%3}, [%4];" \
                 : "=r"(r0), "=r"(r1), "=r"(r2), "=r"(r3) : "r"(addr))

#define CP_ASYNC16(dst, src) \
    asm volatile("cp.async.cg.shared.global [%0], [%1], 16;" \
                 :: "r"((uint32_t)(dst)), "l"(src) : "memory")
#define CP_COMMIT() asm volatile("cp.async.commit_group;" ::: "memory")
#define CP_WAIT1()  asm volatile("cp.async.wait_group 1;" ::: "memory")
#define CP_WAIT0()  asm volatile("cp.async.wait_group 0;" ::: "memory")

// ============================================================================
// Pre-convert fp32 -> packed fp16
// ============================================================================
#define XN4   (MTOK * DMODEL / 4)        // 1048576
#define WN4   (DMODEL * DMODEL / 4)      // 262144

__global__ __launch_bounds__(256)
void cvt_h_kernel(const float4* __restrict__ x,
                  const float4* __restrict__ wq, const float4* __restrict__ wk,
                  const float4* __restrict__ wv, const float4* __restrict__ wo,
                  uint2* __restrict__ xh, uint2* __restrict__ wh)
{
    const int i = blockIdx.x * 256 + threadIdx.x;
    const float4* src;
    uint2* dst;
    if (i < XN4) {
        src = x + i; dst = xh + i;
    } else {
        const int j = i - XN4;
        const int w = j >> 18;
        const int off = j & (WN4 - 1);
        const float4* ws[4] = { wq, wk, wv, wo };
        src = ws[w] + off;
        dst = wh + (size_t)w * WN4 + off;
    }
    float4 v = *src;
    uint2 u;
    u.x = pack_h2(v.x, v.y);
    u.y = pack_h2(v.z, v.w);
    *dst = u;
}

// ============================================================================
// fp16 mma.sync GEMM with ldmatrix fragment loads.
// CTA 128x128, BK=64 halves, 256 thr (8 warps 4x2), warp tile 32x64,
// double-buffered cp.async.
// ============================================================================
#define NCHUNK 16
#define SR32 36
#define TILE_U (128 * SR32)
#define GEMM_SMEM (4 * TILE_U * 4)   // 73728 bytes

template<int STORE_HALF>
__global__ __launch_bounds__(256)
void gemm_h_kernel(const uint32_t* __restrict__ A,
                   const uint32_t* __restrict__ W0, const uint32_t* __restrict__ W1,
                   const uint32_t* __restrict__ W2,
                   const float* __restrict__ b0, const float* __restrict__ b1,
                   const float* __restrict__ b2,
                   void* __restrict__ Y0, void* __restrict__ Y1,
                   void* __restrict__ Y2,
                   float s0, float s1, float s2)
{
    extern __shared__ uint32_t smem[];
    uint32_t* As0 = smem;
    uint32_t* Ws0 = As0 + TILE_U;
    uint32_t* As1 = Ws0 + TILE_U;
    uint32_t* Ws1 = As1 + TILE_U;

    const uint32_t* W = W0; const float* bias = b0; void* Y = Y0; float scale = s0;
    if (blockIdx.z == 1) { W = W1; bias = b1; Y = Y1; scale = s1; }
    else if (blockIdx.z == 2) { W = W2; bias = b2; Y = Y2; scale = s2; }

    const int tid  = threadIdx.x;
    const int wid  = tid >> 5;
    const int lane = tid & 31;
    const int m0 = blockIdx.y * 128;
    const int n0 = blockIdx.x * 128;

    const int m_warp = (wid & 3) * 32;
    const int n_warp = (wid >> 2) * 64;
    const int c4 = lane & 3;
    const int g8 = lane >> 2;

    // ldmatrix lane base offsets (u32 units)
    // A x4: m0=rows0-7@k0, m1=rows8-15@k0, m2=rows0-7@+4, m3=rows8-15@+4
    const uint32_t aL = (uint32_t)((m_warp + (lane & 15)) * SR32 + (lane >> 4) * 4);
    // B x4: m0=rows0-7@k0, m1=rows0-7@+4, m2=rows8-15@k0, m3=rows8-15@+4
    const uint32_t bL = (uint32_t)((n_warp + ((lane >> 4) << 3) + (lane & 7)) * SR32
                                   + ((lane >> 3) & 1) * 4);

    const uint32_t sA0 = smem_u32(As0), sW0 = smem_u32(Ws0);
    const uint32_t sA1 = smem_u32(As1), sW1 = smem_u32(Ws1);

    // loader mapping
    const int rowL = tid >> 1;
    const int hof  = (tid & 1) * 16;
    const uint32_t* Abase = A + (size_t)(m0 + rowL) * DM32 + hof;
    const uint32_t* Wbase = W + (size_t)(n0 + rowL) * DM32 + hof;
    const uint32_t soff = (uint32_t)(rowL * SR32 + hof) * 4u;

#define LOAD_CHUNK(c) do {                                                    \
    uint32_t _da = (((c) & 1) ? sA1 : sA0) + soff;                            \
    uint32_t _dw = (((c) & 1) ? sW1 : sW0) + soff;                            \
    const uint32_t* _ga = Abase + (c) * 32;                                   \
    const uint32_t* _gw = Wbase + (c) * 32;                                   \
    CP_ASYNC16(_da,      _ga);      CP_ASYNC16(_da + 16, _ga + 4);            \
    CP_ASYNC16(_da + 32, _ga + 8);  CP_ASYNC16(_da + 48, _ga + 12);           \
    CP_ASYNC16(_dw,      _gw);      CP_ASYNC16(_dw + 16, _gw + 4);            \
    CP_ASYNC16(_dw + 32, _gw + 8);  CP_ASYNC16(_dw + 48, _gw + 12);           \
    CP_COMMIT();                                                              \
} while (0)

    float acc[2][8][4];
#pragma unroll
    for (int i = 0; i < 2; ++i)
#pragma unroll
        for (int j = 0; j < 8; ++j)
#pragma unroll
            for (int r = 0; r < 4; ++r) acc[i][j][r] = 0.f;

    LOAD_CHUNK(0);
    LOAD_CHUNK(1);

#pragma unroll 1
    for (int c = 0; c < NCHUNK; ++c) {
        if (c + 1 < NCHUNK) CP_WAIT1(); else CP_WAIT0();
        __syncthreads();

        const uint32_t aBuf = ((c & 1) ? sA1 : sA0) + aL * 4u;
        const uint32_t bBuf = ((c & 1) ? sW1 : sW0) + bL * 4u;

#pragma unroll
        for (int ks = 0; ks < 4; ++ks) {
            uint32_t a[2][4];
            LDSM4(a[0][0], a[0][1], a[0][2], a[0][3], aBuf + ks * 32u);
            LDSM4(a[1][0], a[1][1], a[1][2], a[1][3],
                  aBuf + 16u * SR32 * 4u + ks * 32u);
#pragma unroll
            for (int ntp = 0; ntp < 4; ++ntp) {
                uint32_t b[4];
                LDSM4(b[0], b[1], b[2], b[3],
                      bBuf + (uint32_t)(ntp * 16 * SR32) * 4u + ks * 32u);
                mma_f16(acc[0][2 * ntp],     a[0], b[0], b[1]);
                mma_f16(acc[1][2 * ntp],     a[1], b[0], b[1]);
                mma_f16(acc[0][2 * ntp + 1], a[0], b[2], b[3]);
                mma_f16(acc[1][2 * ntp + 1], a[1], b[2], b[3]);
            }
        }

        __syncthreads();
        if (c + 2 < NCHUNK) LOAD_CHUNK(c + 2);
    }
#undef LOAD_CHUNK

#pragma unroll
    for (int mt = 0; mt < 2; ++mt) {
        const int row = m0 + m_warp + mt * 16 + g8;
#pragma unroll
        for (int nt = 0; nt < 8; ++nt) {
            const int col = n0 + n_warp + nt * 8 + c4 * 2;
            const float bx = bias[col], by = bias[col + 1];
            if (STORE_HALF) {
                uint32_t* y0 = (uint32_t*)Y + (size_t)row * DM32 + col / 2;
                uint32_t* y1 = (uint32_t*)Y + (size_t)(row + 8) * DM32 + col / 2;
                *y0 = pack_h2((acc[mt][nt][0] + bx) * scale,
                              (acc[mt][nt][1] + by) * scale);
                *y1 = pack_h2((acc[mt][nt][2] + bx) * scale,
                              (acc[mt][nt][3] + by) * scale);
            } else {
                float* y0 = (float*)Y + (size_t)row * DMODEL + col;
                float* y1 = (float*)Y + (size_t)(row + 8) * DMODEL + col;
                *(float2*)y0 = make_float2(acc[mt][nt][0] + bx, acc[mt][nt][1] + by);
                *(float2*)y1 = make_float2(acc[mt][nt][2] + bx, acc[mt][nt][3] + by);
            }
        }
    }
}

// ============================================================================
// fp16 tensor-core causal flash attention with ldmatrix fragment loads.
// ============================================================================
#define KST 36
#define VST 20

__global__ __launch_bounds__(256)
void attn_h_kernel(const uint32_t* __restrict__ Q, const uint32_t* __restrict__ K,
                   const uint32_t* __restrict__ V, uint32_t* __restrict__ ctx)
{
    __shared__ uint32_t sK[2][32 * KST];
    __shared__ uint32_t sV[2][64 * VST];

    const int tid  = threadIdx.x;
    const int wid  = tid >> 5;
    const int lane = tid & 31;
    const int g8 = lane >> 2;
    const int c4 = lane & 3;

    const int bq = blockIdx.x;
    const int h  = blockIdx.y;
    const int b  = blockIdx.z;
    const int wq0 = bq * 128 + wid * 16;
    const size_t base32 = ((size_t)b * TSEQ) * DM32 + (size_t)h * (DK / 2);

    // B-operand ldmatrix lane base (u32): rows (l>>4)*8 + (l&7), col ((l>>3)&1)*4
    const uint32_t kL = (uint32_t)((((lane >> 4) << 3) + (lane & 7)) * KST
                                   + ((lane >> 3) & 1) * 4);
    const uint32_t vL = (uint32_t)((((lane >> 4) << 3) + (lane & 7)) * VST
                                   + ((lane >> 3) & 1) * 4);
    const uint32_t sKb[2] = { smem_u32(sK[0]) + kL * 4u, smem_u32(sK[1]) + kL * 4u };
    const uint32_t sVb[2] = { smem_u32(sV[0]) + vL * 4u, smem_u32(sV[1]) + vL * 4u };

    // ---- Q fragments ----
    uint32_t qa[4][4];
    {
        const uint32_t* qlo = Q + base32 + (size_t)(wq0 + g8) * DM32;
        const uint32_t* qhi = qlo + 8 * DM32;
#pragma unroll
        for (int ks = 0; ks < 4; ++ks) {
            qa[ks][0] = qlo[8 * ks + c4];
            qa[ks][1] = qhi[8 * ks + c4];
            qa[ks][2] = qlo[8 * ks + c4 + 4];
            qa[ks][3] = qhi[8 * ks + c4 + 4];
        }
    }

    const int ntiles = 4 * bq + 4;

    // loader mappings
    const int kkey = tid >> 3, kx = (tid & 7) * 4;
    const int vkp  = tid & 15, vds = tid >> 4;
    const uint32_t ka0 = smem_u32(sK[0]) + (uint32_t)(kkey * KST + kx) * 4u;
    const uint32_t ka1 = smem_u32(sK[1]) + (uint32_t)(kkey * KST + kx) * 4u;

#define STORE_VT(bufidx, u0, u1) do {                                         \
    uint32_t* Vn = sV[bufidx] + vkp;                                          \
    Vn[(4 * vds + 0) * VST] = __byte_perm((u0).x, (u1).x, 0x5410);            \
    Vn[(4 * vds + 1) * VST] = __byte_perm((u0).x, (u1).x, 0x7632);            \
    Vn[(4 * vds + 2) * VST] = __byte_perm((u0).y, (u1).y, 0x5410);            \
    Vn[(4 * vds + 3) * VST] = __byte_perm((u0).y, (u1).y, 0x7632);            \
} while (0)

    // ---- prologue ----
    {
        const uint32_t* kr = K + base32 + (size_t)kkey * DM32 + kx;
        CP_ASYNC16(ka0, kr);
        CP_COMMIT();
    }
    {
        const uint32_t* v0 = V + base32 + (size_t)(2 * vkp) * DM32 + 2 * vds;
        uint2 u0 = *(const uint2*)v0, u1 = *(const uint2*)(v0 + DM32);
        STORE_VT(0, u0, u1);
    }
    uint2 va, vb;
    {
        const uint32_t* kr = K + base32 + (size_t)(32 + kkey) * DM32 + kx;
        CP_ASYNC16(ka1, kr);
        CP_COMMIT();
        const uint32_t* v0 = V + base32 + (size_t)(32 + 2 * vkp) * DM32 + 2 * vds;
        va = *(const uint2*)v0; vb = *(const uint2*)(v0 + DM32);
    }
    CP_WAIT1();
    __syncthreads();

    float m0 = -1e30f, m1 = -1e30f, l0 = 0.f, l1 = 0.f;
    float o[8][4];
#pragma unroll
    for (int nf = 0; nf < 8; ++nf)
#pragma unroll
        for (int r = 0; r < 4; ++r) o[nf][r] = 0.f;

    const int rlo = wq0 + g8, rhi = rlo + 8;

#pragma unroll 1
    for (int it = 0; it < ntiles; ++it) {
        const int k0 = it * 32;
        const uint32_t kBuf = sKb[it & 1];
        const uint32_t vBuf = sVb[it & 1];

        uint2 na, nb;
        const bool have2 = (it + 2 < ntiles);
        if (have2) {
            const uint32_t* v0 = V + base32
                + (size_t)((it + 2) * 32 + 2 * vkp) * DM32 + 2 * vds;
            na = *(const uint2*)v0; nb = *(const uint2*)(v0 + DM32);
        }

        if (k0 <= wq0 + 15) {
            // ---- S = Q K^T ----
            float s[4][4];
#pragma unroll
            for (int nf = 0; nf < 4; ++nf)
#pragma unroll
                for (int r = 0; r < 4; ++r) s[nf][r] = 0.f;
#pragma unroll
            for (int ks = 0; ks < 4; ++ks) {
#pragma unroll
                for (int nfp = 0; nfp < 2; ++nfp) {
                    uint32_t bfr[4];
                    LDSM4(bfr[0], bfr[1], bfr[2], bfr[3],
                          kBuf + (uint32_t)(nfp * 16 * KST) * 4u + ks * 32u);
                    mma_f16(s[2 * nfp],     qa[ks], bfr[0], bfr[1]);
                    mma_f16(s[2 * nfp + 1], qa[ks], bfr[2], bfr[3]);
                }
            }

            // ---- causal mask (diagonal tiles only) ----
            if (k0 + 31 > wq0) {
#pragma unroll
                for (int nf = 0; nf < 4; ++nf) {
                    const int kg = k0 + nf * 8 + 2 * c4;
                    if (kg     > rlo) s[nf][0] = -1e30f;
                    if (kg + 1 > rlo) s[nf][1] = -1e30f;
                    if (kg     > rhi) s[nf][2] = -1e30f;
                    if (kg + 1 > rhi) s[nf][3] = -1e30f;
                }
            }

            // ---- online softmax (P stays in registers) ----
            float tl = -1e30f, th = -1e30f;
#pragma unroll
            for (int nf = 0; nf < 4; ++nf) {
                tl = fmaxf(tl, fmaxf(s[nf][0], s[nf][1]));
                th = fmaxf(th, fmaxf(s[nf][2], s[nf][3]));
            }
            tl = fmaxf(tl, __shfl_xor_sync(0xffffffffu, tl, 1));
            tl = fmaxf(tl, __shfl_xor_sync(0xffffffffu, tl, 2));
            th = fmaxf(th, __shfl_xor_sync(0xffffffffu, th, 1));
            th = fmaxf(th, __shfl_xor_sync(0xffffffffu, th, 2));

            const float mn0 = fmaxf(m0, tl), mn1 = fmaxf(m1, th);
            const float cr0 = __expf(m0 - mn0), cr1 = __expf(m1 - mn1);
            float e[4][4];
            float sl = 0.f, sh = 0.f;
#pragma unroll
            for (int nf = 0; nf < 4; ++nf) {
                e[nf][0] = __expf(s[nf][0] - mn0);
                e[nf][1] = __expf(s[nf][1] - mn0);
                e[nf][2] = __expf(s[nf][2] - mn1);
                e[nf][3] = __expf(s[nf][3] - mn1);
                sl += e[nf][0] + e[nf][1];
                sh += e[nf][2] + e[nf][3];
            }
            sl += __shfl_xor_sync(0xffffffffu, sl, 1);
            sl += __shfl_xor_sync(0xffffffffu, sl, 2);
            sh += __shfl_xor_sync(0xffffffffu, sh, 1);
            sh += __shfl_xor_sync(0xffffffffu, sh, 2);
            l0 = l0 * cr0 + sl;  l1 = l1 * cr1 + sh;
            m0 = mn0;  m1 = mn1;
#pragma unroll
            for (int nf = 0; nf < 8; ++nf) {
                o[nf][0] *= cr0; o[nf][1] *= cr0;
                o[nf][2] *= cr1; o[nf][3] *= cr1;
            }

            // ---- O += P V ----
#pragma unroll
            for (int ks = 0; ks < 2; ++ks) {
                uint32_t a[4];
                a[0] = pack_h2(e[2 * ks][0],     e[2 * ks][1]);
                a[1] = pack_h2(e[2 * ks][2],     e[2 * ks][3]);
                a[2] = pack_h2(e[2 * ks + 1][0], e[2 * ks + 1][1]);
                a[3] = pack_h2(e[2 * ks + 1][2], e[2 * ks + 1][3]);
#pragma unroll
                for (int nfp = 0; nfp < 4; ++nfp) {
                    uint32_t bfr[4];
                    LDSM4(bfr[0], bfr[1], bfr[2], bfr[3],
                          vBuf + (uint32_t)(nfp * 16 * VST) * 4u + ks * 32u);
                    mma_f16(o[2 * nfp],     a, bfr[0], bfr[1]);
                    mma_f16(o[2 * nfp + 1], a, bfr[2], bfr[3]);
                }
            }
        }

        // ---- pipeline advance ----
        if (it + 1 < ntiles) {
            CP_WAIT0();
            __syncthreads();
            STORE_VT((it + 1) & 1, va, vb);
            if (have2) {
                const uint32_t* kr = K + base32
                    + (size_t)((it + 2) * 32 + kkey) * DM32 + kx;
                CP_ASYNC16((it & 1) ? ka1 : ka0, kr);
                CP_COMMIT();
                va = na; vb = nb;
            }
            __syncthreads();
        }
    }
#undef STORE_VT

    // ---- epilogue: ctx as packed fp16 ----
    const float inv0 = 1.f / l0, inv1 = 1.f / l1;
    uint32_t* olo = ctx + base32 + (size_t)rlo * DM32;
    uint32_t* ohi = ctx + base32 + (size_t)rhi * DM32;
#pragma unroll
    for (int nf = 0; nf < 8; ++nf) {
        olo[nf * 4 + c4] = pack_h2(o[nf][0] * inv0, o[nf][1] * inv0);
        ohi[nf * 4 + c4] = pack_h2(o[nf][2] * inv1, o[nf][3] * inv1);
    }
}

// ============================================================================
// launch
// ============================================================================
extern "C" void kernel_launch(void* const* d_in, const int* in_sizes, int n_in,
                              void* d_out, int out_size)
{
    const float* x  = (const float*)d_in[0];
    const float* Wq = (const float*)d_in[1];
    const float* bq = (const float*)d_in[2];
    const float* Wk = (const float*)d_in[3];
    const float* bk = (const float*)d_in[4];
    const float* Wv = (const float*)d_in[5];
    const float* bv = (const float*)d_in[6];
    const float* Wo = (const float*)d_in[7];
    const float* bo = (const float*)d_in[8];
    float* out = (float*)d_out;

    uint32_t *xh, *wh, *qp, *kp, *vp, *cp;
    cudaGetSymbolAddress((void**)&xh, g_xh);
    cudaGetSymbolAddress((void**)&wh, g_Wh);
    cudaGetSymbolAddress((void**)&qp, g_Q);
    cudaGetSymbolAddress((void**)&kp, g_K);
    cudaGetSymbolAddress((void**)&vp, g_V);
    cudaGetSymbolAddress((void**)&cp, g_ctx);

    cudaFuncSetAttribute(gemm_h_kernel<1>,
                         cudaFuncAttributeMaxDynamicSharedMemorySize, GEMM_SMEM);
    cudaFuncSetAttribute(gemm_h_kernel<0>,
                         cudaFuncAttributeMaxDynamicSharedMemorySize, GEMM_SMEM);

    // 1) pre-convert x + weights to packed fp16
    cvt_h_kernel<<<(XN4 + 4 * WN4) / 256, 256>>>(
        (const float4*)x, (const float4*)Wq, (const float4*)Wk,
        (const float4*)Wv, (const float4*)Wo, (uint2*)xh, (uint2*)wh);

    // 2) fused QKV projections (Q scaled by 1/sqrt(dk))
    const size_t W32 = (size_t)DMODEL * DM32;
    dim3 qkv_grid(DMODEL / 128, MTOK / 128, 3);
    gemm_h_kernel<1><<<qkv_grid, 256, GEMM_SMEM>>>(
        xh, wh, wh + W32, wh + 2 * W32,
        bq, bk, bv, qp, kp, vp, 0.125f, 1.f, 1.f);

    // 3) attention
    dim3 agrid(TSEQ / 128, NHEADS, BDIM);
    attn_h_kernel<<<agrid, 256>>>(qp, kp, vp, cp);

    // 4) output projection -> fp32 d_out
    dim3 o_grid(DMODEL / 128, MTOK / 128, 1);
    gemm_h_kernel<0><<<o_grid, 256, GEMM_SMEM>>>(
        cp, wh + 3 * W32, wh, wh,
        bo, bo, bo, out, out, out, 1.f, 1.f, 1.f);
}